// round 1
// baseline (speedup 1.0000x reference)
#include <cuda_runtime.h>
#include <cstdint>

// Problem constants (fixed by the dataset)
#define BB 4096
#define LL 256
#define HH 32

#define WARPS_PER_BLOCK 4
#define THREADS_PER_BLOCK (WARPS_PER_BLOCK * 32)
#define BATCH_PER_WARP 4            // 4 groups of 8 lanes
#define BATCH_PER_BLOCK (WARPS_PER_BLOCK * BATCH_PER_WARP)  // 16

// ---------- f32x2 packed helpers (Blackwell packed fp32 pipe) ----------
__device__ __forceinline__ unsigned long long pack2(float a, float b) {
    unsigned long long r;
    asm("mov.b64 %0, {%1, %2};" : "=l"(r)
        : "r"(__float_as_uint(a)), "r"(__float_as_uint(b)));
    return r;
}
__device__ __forceinline__ void unpack2(unsigned long long v, float& a, float& b) {
    unsigned int x, y;
    asm("mov.b64 {%0, %1}, %2;" : "=r"(x), "=r"(y) : "l"(v));
    a = __uint_as_float(x);
    b = __uint_as_float(y);
}
__device__ __forceinline__ unsigned long long fma2(unsigned long long a,
                                                   unsigned long long b,
                                                   unsigned long long c) {
    unsigned long long d;
    asm("fma.rn.f32x2 %0, %1, %2, %3;" : "=l"(d) : "l"(a), "l"(b), "l"(c));
    return d;
}
__device__ __forceinline__ unsigned long long add2(unsigned long long a,
                                                   unsigned long long b) {
    unsigned long long d;
    asm("add.rn.f32x2 %0, %1, %2;" : "=l"(d) : "l"(a), "l"(b));
    return d;
}

// ---------- fast-but-accurate activations (EX2-based, ~1e-7 rel) ----------
__device__ __forceinline__ float sigmoid_f(float x) {
    return __fdividef(1.0f, 1.0f + __expf(-x));
}
__device__ __forceinline__ float tanh_f(float x) {
    float e = __expf(-2.0f * x);
    return __fdividef(1.0f - e, 1.0f + e);
}

// Warp layout:
//   lane = 32 lanes = 4 groups of 8.  group g = lane>>3 handles batch element
//   (warp*4 + g).  Within a group, lane jj = lane&7 owns hidden units
//   J = {jj, jj+8, jj+16, jj+24}.
// Smem Wh is packed as float4 quads per (k, j): (Wh[k][j], Wh[k][j+32],
//   Wh[k][j+64], Wh[k][j+96])  -> one LDS.128 yields both f32x2 operands.
__global__ void __launch_bounds__(THREADS_PER_BLOCK)
lstm_kernel(const int* __restrict__ x,       // [B, L] spins in {0,1}
            const float* __restrict__ Wi,    // [2, 128]
            const float* __restrict__ Wh,    // [32, 128]
            const float* __restrict__ bh,    // [128]
            const float* __restrict__ Wo,    // [32, 2]
            const float* __restrict__ bo,    // [2]
            float* __restrict__ out)         // [B]
{
    __shared__ ulonglong2 s_wh[32 * 32];    // [k][j] packed gate quads, 16 KB
    __shared__ ulonglong2 s_init[3 * 32];   // [sel][j]: Wi[0]+bh, Wi[1]+bh, bh
    __shared__ unsigned char s_x[BATCH_PER_BLOCK * LL];  // spins, 4 KB

    const int tid = threadIdx.x;

    // ---- setup: pack Wh into quads ----
    {
        float* whf = reinterpret_cast<float*>(s_wh);
        for (int idx = tid; idx < 32 * 128; idx += THREADS_PER_BLOCK) {
            int k = idx >> 7;
            int col = idx & 127;
            int j = col & 31;
            int g = col >> 5;
            whf[(k * 32 + j) * 4 + g] = Wh[idx];
        }
        float* inf = reinterpret_cast<float*>(s_init);
        for (int idx = tid; idx < 3 * 128; idx += THREADS_PER_BLOCK) {
            int s = idx >> 7;          // 0,1 = spin one-hot rows, 2 = zeros (t=0)
            int col = idx & 127;
            int j = col & 31;
            int g = col >> 5;
            float v = bh[col];
            if (s < 2) v += Wi[s * 128 + col];
            inf[(s * 32 + j) * 4 + g] = v;
        }
        const int base_b = blockIdx.x * BATCH_PER_BLOCK;
        for (int idx = tid; idx < BATCH_PER_BLOCK * LL; idx += THREADS_PER_BLOCK) {
            // idx = b_local*256 + t; gmem read is coalesced across t
            s_x[idx] = (unsigned char)x[base_b * LL + idx];
        }
    }
    __syncthreads();

    const int lane = tid & 31;
    const int warp = tid >> 5;
    const int jj = lane & 7;        // lane-in-group: which unit set
    const int grp = lane >> 3;      // group = batch within warp
    const int gbase = lane & 24;    // group base lane for shuffles
    const int b_local = warp * BATCH_PER_WARP + grp;
    const int b_glob = blockIdx.x * BATCH_PER_BLOCK + b_local;
    const unsigned char* xb = s_x + b_local * LL;

    // output-head weights for my 4 units
    float wo0[4], wo1[4];
#pragma unroll
    for (int m = 0; m < 4; m++) {
        int j = jj + 8 * m;
        wo0[m] = Wo[2 * j + 0];
        wo1[m] = Wo[2 * j + 1];
    }
    const float bo0 = bo[0];
    const float bo1 = bo[1];

    float h[4] = {0.f, 0.f, 0.f, 0.f};
    float c[4] = {0.f, 0.f, 0.f, 0.f};
    float logp = 0.f;
    int sel = 2;  // t=0: zero input row

    for (int t = 0; t < LL; ++t) {
        // ---- gate accumulators init: table row (Wi[sel] + bh) ----
        unsigned long long accif[4], accgo[4];
#pragma unroll
        for (int m = 0; m < 4; m++) {
            ulonglong2 v = s_init[sel * 32 + jj + 8 * m];
            accif[m] = v.x;   // (i, f)
            accgo[m] = v.y;   // (g, o)
        }

        // ---- recurrence: gates += h @ Wh ----
#pragma unroll
        for (int k = 0; k < 32; k++) {
            float hk = __shfl_sync(0xffffffffu, h[k >> 3], gbase | (k & 7));
            unsigned long long hk2 = pack2(hk, hk);
#pragma unroll
            for (int m = 0; m < 4; m++) {
                ulonglong2 w = s_wh[k * 32 + jj + 8 * m];
                accif[m] = fma2(hk2, w.x, accif[m]);
                accgo[m] = fma2(hk2, w.y, accgo[m]);
            }
        }

        // ---- activations + state update + output partials ----
        float p0 = 0.f, p1 = 0.f;
#pragma unroll
        for (int m = 0; m < 4; m++) {
            float gi, gf, gg, go;
            unpack2(accif[m], gi, gf);
            unpack2(accgo[m], gg, go);
            float si = sigmoid_f(gi);
            float sf = sigmoid_f(gf);
            float so = sigmoid_f(go);
            float tg = tanh_f(gg);
            float cn = fmaf(sf, c[m], si * tg);
            c[m] = cn;
            float hn = so * tanh_f(cn);
            h[m] = hn;
            p0 = fmaf(hn, wo0[m], p0);
            p1 = fmaf(hn, wo1[m], p1);
        }

        // ---- reduce (out0, out1) over the 8 lanes of the group ----
        unsigned long long pp = pack2(p0, p1);
#pragma unroll
        for (int d = 4; d > 0; d >>= 1) {
            unsigned long long q = __shfl_xor_sync(0xffffffffu, pp, d);
            pp = add2(pp, q);
        }
        unpack2(pp, p0, p1);

        // ---- elu + gathered log-softmax ----
        float o0 = p0 + bo0;
        float o1 = p1 + bo1;
        float e0 = (o0 > 0.f) ? o0 : (__expf(o0) - 1.f);
        float e1 = (o1 > 0.f) ? o1 : (__expf(o1) - 1.f);
        float mx = fmaxf(e0, e1);
        float lse = mx + __logf(__expf(e0 - mx) + __expf(e1 - mx));
        int cur = (int)xb[t];
        logp += (cur ? e1 : e0) - lse;
        sel = cur;  // next step's input one-hot row
    }

    if (jj == 0) {
        out[b_glob] = 0.5f * logp;
    }
}

extern "C" void kernel_launch(void* const* d_in, const int* in_sizes, int n_in,
                              void* d_out, int out_size) {
    const int* x = (const int*)d_in[0];
    const float* Wi = (const float*)d_in[1];
    const float* Wh = (const float*)d_in[2];
    const float* bh = (const float*)d_in[3];
    const float* Wo = (const float*)d_in[4];
    const float* bo = (const float*)d_in[5];
    float* out = (float*)d_out;

    const int batch = in_sizes[0] / LL;          // 4096
    const int blocks = batch / BATCH_PER_BLOCK;  // 256

    lstm_kernel<<<blocks, THREADS_PER_BLOCK>>>(x, Wi, Wh, bh, Wo, bo, out);
}

// round 3
// speedup vs baseline: 1.8139x; 1.8139x over previous
#include <cuda_runtime.h>
#include <cstdint>

// Problem constants (fixed by the dataset)
#define LL 256

#define WARPS_PER_BLOCK 4
#define THREADS_PER_BLOCK (WARPS_PER_BLOCK * 32)   // 1 warp = 1 batch element

// ---------- f32x2 packed helpers (Blackwell packed fp32 pipe) ----------
__device__ __forceinline__ unsigned long long pack2(float a, float b) {
    unsigned long long r;
    asm("mov.b64 %0, {%1, %2};" : "=l"(r)
        : "r"(__float_as_uint(a)), "r"(__float_as_uint(b)));
    return r;
}
__device__ __forceinline__ void unpack2(unsigned long long v, float& a, float& b) {
    unsigned int x, y;
    asm("mov.b64 {%0, %1}, %2;" : "=r"(x), "=r"(y) : "l"(v));
    a = __uint_as_float(x);
    b = __uint_as_float(y);
}
__device__ __forceinline__ unsigned long long fma2(unsigned long long a,
                                                   unsigned long long b,
                                                   unsigned long long c) {
    unsigned long long d;
    asm("fma.rn.f32x2 %0, %1, %2, %3;" : "=l"(d) : "l"(a), "l"(b), "l"(c));
    return d;
}
__device__ __forceinline__ unsigned long long add2(unsigned long long a,
                                                   unsigned long long b) {
    unsigned long long d;
    asm("add.rn.f32x2 %0, %1, %2;" : "=l"(d) : "l"(a), "l"(b));
    return d;
}

// HW tanh (MUFU.TANH, sm_75+): ~1e-4 abs error, 1 MUFU op
__device__ __forceinline__ float tanh_fast(float x) {
    float y;
    asm("tanh.approx.f32 %0, %1;" : "=f"(y) : "f"(x));
    return y;
}
// sigmoid(x) = 0.5*tanh(0.5x) + 0.5   (1 MUFU + 2 FMA-class ops)
__device__ __forceinline__ float sigmoid_fast(float x) {
    return fmaf(0.5f, tanh_fast(0.5f * x), 0.5f);
}

// Layout: warp = one batch element. Lane j owns hidden unit j.
// Wh column weights for unit j live in REGISTERS as f32x2 pairs:
//   wif[k] = (Wh[k][j],   Wh[k][32+j])   -> (i,f) gates
//   wgo[k] = (Wh[k][64+j], Wh[k][96+j])  -> (g,o) gates
// Per step: broadcast h_k via SHFL (no smem crossbar traffic), 64 FFMA2.
__global__ void __launch_bounds__(THREADS_PER_BLOCK, 3)
lstm_kernel(const int* __restrict__ x,       // [B, L] spins in {0,1}
            const float* __restrict__ Wi,    // [2, 128]
            const float* __restrict__ Wh,    // [32, 128]
            const float* __restrict__ bh,    // [128]
            const float* __restrict__ Wo,    // [32, 2]
            const float* __restrict__ bo,    // [2]
            float* __restrict__ out)         // [B]
{
    __shared__ ulonglong2 s_init[3 * 32];  // [sel][lane]: (Wi[sel]+bh) packed quads
    __shared__ unsigned char s_x[WARPS_PER_BLOCK * LL];

    const int tid = threadIdx.x;
    const int lane = tid & 31;
    const int warp = tid >> 5;
    const int b_glob = blockIdx.x * WARPS_PER_BLOCK + warp;

    // ---- setup: init-row table (Wi[sel] + bh; row 2 = bh only for t=0) ----
    if (tid < 96) {
        int s = tid >> 5;        // 0,1,2
        int j = tid & 31;
        float bi = bh[j], bf = bh[32 + j], bg = bh[64 + j], bo_ = bh[96 + j];
        float ai = bi, af = bf, ag = bg, ao = bo_;
        if (s < 2) {
            ai += Wi[s * 128 + j];
            af += Wi[s * 128 + 32 + j];
            ag += Wi[s * 128 + 64 + j];
            ao += Wi[s * 128 + 96 + j];
        }
        ulonglong2 v;
        v.x = pack2(ai, af);
        v.y = pack2(ag, ao);
        s_init[s * 32 + j] = v;
    }
    {
        const int base = blockIdx.x * WARPS_PER_BLOCK * LL;
        for (int idx = tid; idx < WARPS_PER_BLOCK * LL; idx += THREADS_PER_BLOCK)
            s_x[idx] = (unsigned char)x[base + idx];
    }
    __syncthreads();

    const unsigned char* xb = s_x + warp * LL;
    const int j = lane;

    // ---- register-resident recurrent weights ----
    unsigned long long wif[32], wgo[32];
#pragma unroll
    for (int k = 0; k < 32; k++) {
        const float* r = Wh + k * 128;
        wif[k] = pack2(r[j], r[32 + j]);
        wgo[k] = pack2(r[64 + j], r[96 + j]);
    }
    const float wo0 = Wo[2 * j];
    const float wo1 = Wo[2 * j + 1];
    const float bo0 = bo[0];
    const float bo1 = bo[1];

    float h = 0.f, c = 0.f, logp = 0.f;

    // t=0 gate init: bh-only row (row 2)
    ulonglong2 v0 = s_init[2 * 32 + lane];
    unsigned long long selif = v0.x;
    unsigned long long selgo = v0.y;
    const unsigned long long zero2 = 0ull;

    for (int t = 0; t < LL; t++) {
        // 4 independent accumulator chains (no FMA dep stalls)
        unsigned long long aif_a = selif, aif_b = zero2;
        unsigned long long ago_a = selgo, ago_b = zero2;

#pragma unroll
        for (int k = 0; k < 32; k += 2) {
            float hk0 = __shfl_sync(0xffffffffu, h, k);
            float hk1 = __shfl_sync(0xffffffffu, h, k + 1);
            unsigned long long h0 = pack2(hk0, hk0);
            unsigned long long h1 = pack2(hk1, hk1);
            aif_a = fma2(h0, wif[k], aif_a);
            ago_a = fma2(h0, wgo[k], ago_a);
            aif_b = fma2(h1, wif[k + 1], aif_b);
            ago_b = fma2(h1, wgo[k + 1], ago_b);
        }
        unsigned long long aif = add2(aif_a, aif_b);
        unsigned long long ago = add2(ago_a, ago_b);

        float gi, gf, gg, go;
        unpack2(aif, gi, gf);
        unpack2(ago, gg, go);
        float si = sigmoid_fast(gi);
        float sf = sigmoid_fast(gf);
        float so = sigmoid_fast(go);
        float tg = tanh_fast(gg);
        c = fmaf(sf, c, si * tg);
        h = so * tanh_fast(c);

        // output projection: reduce (h*wo0, h*wo1) across 32 lanes
        unsigned long long pp = pack2(h * wo0, h * wo1);
#pragma unroll
        for (int d = 16; d > 0; d >>= 1) {
            unsigned long long q = __shfl_xor_sync(0xffffffffu, pp, d);
            pp = add2(pp, q);
        }
        float p0, p1;
        unpack2(pp, p0, p1);

        // elu + gathered log-softmax (uniform across the warp)
        float o0 = p0 + bo0;
        float o1 = p1 + bo1;
        float e0 = (o0 > 0.f) ? o0 : (__expf(o0) - 1.f);
        float e1 = (o1 > 0.f) ? o1 : (__expf(o1) - 1.f);
        float mx = fmaxf(e0, e1);
        float lse = mx + __logf(__expf(e0 - mx) + __expf(e1 - mx));
        int cur = (int)xb[t];
        logp += (cur ? e1 : e0) - lse;

        // next step's gate-init row (LDS.128, overlaps with everything)
        ulonglong2 vn = s_init[cur * 32 + lane];
        selif = vn.x;
        selgo = vn.y;
    }

    if (lane == 0) {
        out[b_glob] = 0.5f * logp;
    }
}

extern "C" void kernel_launch(void* const* d_in, const int* in_sizes, int n_in,
                              void* d_out, int out_size) {
    const int* x = (const int*)d_in[0];
    const float* Wi = (const float*)d_in[1];
    const float* Wh = (const float*)d_in[2];
    const float* bh = (const float*)d_in[3];
    const float* Wo = (const float*)d_in[4];
    const float* bo = (const float*)d_in[5];
    float* out = (float*)d_out;

    const int batch = in_sizes[0] / LL;                 // 4096
    const int blocks = batch / WARPS_PER_BLOCK;         // 1024

    lstm_kernel<<<blocks, THREADS_PER_BLOCK>>>(x, Wi, Wh, bh, Wo, bo, out);
}

// round 5
// speedup vs baseline: 2.0629x; 1.1373x over previous
#include <cuda_runtime.h>
#include <cstdint>

// Problem constants (fixed by the dataset)
#define LL 256

#define WARPS_PER_BLOCK 4
#define THREADS_PER_BLOCK (WARPS_PER_BLOCK * 32)   // 1 warp = 1 batch element

// ---------- f32x2 packed helpers (Blackwell packed fp32 pipe) ----------
__device__ __forceinline__ unsigned long long pack2(float a, float b) {
    unsigned long long r;
    asm("mov.b64 %0, {%1, %2};" : "=l"(r)
        : "r"(__float_as_uint(a)), "r"(__float_as_uint(b)));
    return r;
}
__device__ __forceinline__ void unpack2(unsigned long long v, float& a, float& b) {
    unsigned int x, y;
    asm("mov.b64 {%0, %1}, %2;" : "=r"(x), "=r"(y) : "l"(v));
    a = __uint_as_float(x);
    b = __uint_as_float(y);
}
__device__ __forceinline__ unsigned long long fma2(unsigned long long a,
                                                   unsigned long long b,
                                                   unsigned long long c) {
    unsigned long long d;
    asm("fma.rn.f32x2 %0, %1, %2, %3;" : "=l"(d) : "l"(a), "l"(b), "l"(c));
    return d;
}
__device__ __forceinline__ unsigned long long add2(unsigned long long a,
                                                   unsigned long long b) {
    unsigned long long d;
    asm("add.rn.f32x2 %0, %1, %2;" : "=l"(d) : "l"(a), "l"(b));
    return d;
}

// HW tanh (MUFU.TANH): ~1e-4 abs error, 1 MUFU op
__device__ __forceinline__ float tanh_fast(float x) {
    float y;
    asm("tanh.approx.f32 %0, %1;" : "=f"(y) : "f"(x));
    return y;
}

// Layout: warp = one batch element. Lane j owns hidden unit j.
// Wh column weights for unit j live in REGISTERS as f32x2 pairs.
// Sigmoid prescale (x0.5 on i,f,o gate columns) is folded into the weights,
// so sigmoid(g) = fma(0.5, tanh(g'), 0.5) with g' the prescaled accumulator.
// h-broadcast: lane j stores (h_j, h_j) once (STS.64); all lanes read the
// whole table via broadcast LDS.128 (same-address -> conflict-free, and the
// 64-bit halves are ready-made f32x2 operands: no pack MOVs, no SHFLs).
// Output head: both dot products reduced together with one 64-bit butterfly.
__global__ void __launch_bounds__(THREADS_PER_BLOCK, 3)
lstm_kernel(const int* __restrict__ x,       // [B, L] spins in {0,1}
            const float* __restrict__ Wi,    // [2, 128]
            const float* __restrict__ Wh,    // [32, 128]
            const float* __restrict__ bh,    // [128]
            const float* __restrict__ Wo,    // [32, 2]
            const float* __restrict__ bo,    // [2]
            float* __restrict__ out)         // [B]
{
    __shared__ ulonglong2 s_init[3 * 32];  // [sel][lane]: prescaled (Wi[sel]+bh)
    __shared__ unsigned long long s_h[WARPS_PER_BLOCK][2][32];  // (h,h) pairs, dbl-buf
    __shared__ unsigned char s_x[WARPS_PER_BLOCK * LL];

    const int tid = threadIdx.x;
    const int lane = tid & 31;
    const int warp = tid >> 5;
    const int b_glob = blockIdx.x * WARPS_PER_BLOCK + warp;

    // ---- setup: init-row table (prescaled: 0.5 on i,f,o; 1.0 on g) ----
    if (tid < 96) {
        int s = tid >> 5;        // 0,1 = spin rows, 2 = bh-only (t=0)
        int j = tid & 31;
        float ai = bh[j], af = bh[32 + j], ag = bh[64 + j], ao = bh[96 + j];
        if (s < 2) {
            ai += Wi[s * 128 + j];
            af += Wi[s * 128 + 32 + j];
            ag += Wi[s * 128 + 64 + j];
            ao += Wi[s * 128 + 96 + j];
        }
        ulonglong2 v;
        v.x = pack2(0.5f * ai, 0.5f * af);
        v.y = pack2(ag, 0.5f * ao);
        s_init[s * 32 + j] = v;
    }
    {
        const int base = blockIdx.x * WARPS_PER_BLOCK * LL;
        for (int idx = tid; idx < WARPS_PER_BLOCK * LL; idx += THREADS_PER_BLOCK)
            s_x[idx] = (unsigned char)x[base + idx];
    }
    __syncthreads();

    const unsigned char* xb = s_x + warp * LL;
    const int j = lane;

    // ---- register-resident recurrent weights (prescaled) ----
    unsigned long long wif[32], wgo[32];
#pragma unroll
    for (int k = 0; k < 32; k++) {
        const float* r = Wh + k * 128;
        wif[k] = pack2(0.5f * r[j], 0.5f * r[32 + j]);
        wgo[k] = pack2(r[64 + j], 0.5f * r[96 + j]);
    }
    const float wo0 = Wo[2 * j];
    const float wo1 = Wo[2 * j + 1];
    const float bo0 = bo[0];
    const float bo1 = bo[1];

    float h = 0.f, c = 0.f, logp = 0.f;

    // t=0 gate init: bh-only row (row 2)
    ulonglong2 v0 = s_init[2 * 32 + lane];
    unsigned long long selif = v0.x;
    unsigned long long selgo = v0.y;

    const ulonglong2* hb0 = reinterpret_cast<const ulonglong2*>(s_h[warp][0]);
    const ulonglong2* hb1 = reinterpret_cast<const ulonglong2*>(s_h[warp][1]);

#pragma unroll 1
    for (int t = 0; t < LL; t += 2) {
#pragma unroll
        for (int half = 0; half < 2; half++) {
            // publish my (h, h) pair to this step's buffer
            unsigned long long hpair = pack2(h, h);
            s_h[warp][half][lane] = hpair;
            __syncwarp();
            const ulonglong2* hb = half ? hb1 : hb0;

            // 4 independent accumulator chains
            unsigned long long aif_a = selif, aif_b = 0ull;
            unsigned long long ago_a = selgo, ago_b = 0ull;
#pragma unroll
            for (int k = 0; k < 32; k += 2) {
                ulonglong2 hh = hb[k >> 1];   // broadcast LDS.128: (hk,hk),(hk+1,hk+1)
                aif_a = fma2(hh.x, wif[k], aif_a);
                ago_a = fma2(hh.x, wgo[k], ago_a);
                aif_b = fma2(hh.y, wif[k + 1], aif_b);
                ago_b = fma2(hh.y, wgo[k + 1], ago_b);
            }
            unsigned long long aif = add2(aif_a, aif_b);
            unsigned long long ago = add2(ago_a, ago_b);

            float gi, gf, gg, go;
            unpack2(aif, gi, gf);
            unpack2(ago, gg, go);
            float si = fmaf(0.5f, tanh_fast(gi), 0.5f);   // prescaled sigmoid
            float sf = fmaf(0.5f, tanh_fast(gf), 0.5f);
            float so = fmaf(0.5f, tanh_fast(go), 0.5f);
            float tg = tanh_fast(gg);
            c = fmaf(sf, c, si * tg);
            h = so * tanh_fast(c);

            // output head: both dot products in one 64-bit butterfly reduction
            unsigned long long pp = pack2(h * wo0, h * wo1);
#pragma unroll
            for (int d = 16; d > 0; d >>= 1) {
                unsigned long long q = __shfl_xor_sync(0xffffffffu, pp, d);
                pp = add2(pp, q);
            }
            float p0, p1;
            unpack2(pp, p0, p1);
            p0 += bo0;
            p1 += bo1;

            // elu + 2-class gathered log-softmax: -log1p(exp(e_other - e_sel))
            float e0 = (p0 > 0.f) ? p0 : (__expf(p0) - 1.f);
            float e1 = (p1 > 0.f) ? p1 : (__expf(p1) - 1.f);
            int cur = (int)xb[t + half];
            float d = cur ? (e0 - e1) : (e1 - e0);   // e_other - e_sel
            logp -= __logf(1.f + __expf(d));

            // next step's gate-init row
            ulonglong2 vn = s_init[cur * 32 + lane];
            selif = vn.x;
            selgo = vn.y;
        }
    }

    if (lane == 0) {
        out[b_glob] = 0.5f * logp;
    }
}

extern "C" void kernel_launch(void* const* d_in, const int* in_sizes, int n_in,
                              void* d_out, int out_size) {
    const int* x = (const int*)d_in[0];
    const float* Wi = (const float*)d_in[1];
    const float* Wh = (const float*)d_in[2];
    const float* bh = (const float*)d_in[3];
    const float* Wo = (const float*)d_in[4];
    const float* bo = (const float*)d_in[5];
    float* out = (float*)d_out;

    const int batch = in_sizes[0] / LL;                 // 4096
    const int blocks = batch / WARPS_PER_BLOCK;         // 1024

    lstm_kernel<<<blocks, THREADS_PER_BLOCK>>>(x, Wi, Wh, bh, Wo, bo, out);
}

// round 6
// speedup vs baseline: 2.1524x; 1.0434x over previous
#include <cuda_runtime.h>
#include <cstdint>

// Problem constants (fixed by the dataset)
#define LL 256

#define WARPS_PER_BLOCK 4
#define THREADS_PER_BLOCK (WARPS_PER_BLOCK * 32)   // 1 warp = 1 batch element

// ---------- f32x2 packed helpers (Blackwell packed fp32 pipe) ----------
__device__ __forceinline__ unsigned long long pack2(float a, float b) {
    unsigned long long r;
    asm("mov.b64 %0, {%1, %2};" : "=l"(r)
        : "r"(__float_as_uint(a)), "r"(__float_as_uint(b)));
    return r;
}
__device__ __forceinline__ void unpack2(unsigned long long v, float& a, float& b) {
    unsigned int x, y;
    asm("mov.b64 {%0, %1}, %2;" : "=r"(x), "=r"(y) : "l"(v));
    a = __uint_as_float(x);
    b = __uint_as_float(y);
}
__device__ __forceinline__ unsigned long long fma2(unsigned long long a,
                                                   unsigned long long b,
                                                   unsigned long long c) {
    unsigned long long d;
    asm("fma.rn.f32x2 %0, %1, %2, %3;" : "=l"(d) : "l"(a), "l"(b), "l"(c));
    return d;
}
__device__ __forceinline__ unsigned long long add2(unsigned long long a,
                                                   unsigned long long b) {
    unsigned long long d;
    asm("add.rn.f32x2 %0, %1, %2;" : "=l"(d) : "l"(a), "l"(b));
    return d;
}

// HW tanh (MUFU.TANH): ~1e-4 abs error, 1 MUFU op
__device__ __forceinline__ float tanh_fast(float x) {
    float y;
    asm("tanh.approx.f32 %0, %1;" : "=f"(y) : "f"(x));
    return y;
}

// Deferred output-head work: butterfly-reduce the staged (h*wo0, h*wo1) pair,
// then elu + 2-class gathered log-softmax. `wmask` (0 on the priming call)
// multiplies the contribution so the bogus initial pend is dropped.
__device__ __forceinline__ float head_update(unsigned long long pp, int cur,
                                             float bo0, float bo1,
                                             float wmask, float logp) {
#pragma unroll
    for (int d = 16; d > 0; d >>= 1) {
        unsigned long long q = __shfl_xor_sync(0xffffffffu, pp, d);
        pp = add2(pp, q);
    }
    float p0, p1;
    unpack2(pp, p0, p1);
    p0 += bo0;
    p1 += bo1;
    float e0 = (p0 > 0.f) ? p0 : (__expf(p0) - 1.f);
    float e1 = (p1 > 0.f) ? p1 : (__expf(p1) - 1.f);
    float d = cur ? (e0 - e1) : (e1 - e0);   // e_other - e_sel
    return fmaf(wmask, -__logf(1.f + __expf(d)), logp);
}

// Layout: warp = one batch element. Lane j owns hidden unit j.
// Wh column weights for unit j live in REGISTERS as f32x2 pairs (prescaled:
// x0.5 on i,f,o gate columns so sigmoid(g) = fma(0.5, tanh(g'), 0.5)).
// h-broadcast: lane j stores (h_j, h_j) once (STS.64); all lanes read the
// table via broadcast LDS.128 (same-address, conflict-free, halves are
// ready-made f32x2 operands). Output head is SOFTWARE-PIPELINED: the SHFL
// butterfly + softmax of step t executes during step t+1's FMA loop, so its
// ~150 cyc of SHFL/MUFU latency is off the recurrence critical path.
__global__ void __launch_bounds__(THREADS_PER_BLOCK, 3)
lstm_kernel(const int* __restrict__ x,       // [B, L] spins in {0,1}
            const float* __restrict__ Wi,    // [2, 128]
            const float* __restrict__ Wh,    // [32, 128]
            const float* __restrict__ bh,    // [128]
            const float* __restrict__ Wo,    // [32, 2]
            const float* __restrict__ bo,    // [2]
            float* __restrict__ out)         // [B]
{
    __shared__ ulonglong2 s_init[3 * 32];  // [sel][lane]: prescaled (Wi[sel]+bh)
    __shared__ unsigned long long s_h[WARPS_PER_BLOCK][2][32];  // (h,h) pairs, dbl-buf
    __shared__ unsigned char s_x[WARPS_PER_BLOCK * LL];

    const int tid = threadIdx.x;
    const int lane = tid & 31;
    const int warp = tid >> 5;
    const int b_glob = blockIdx.x * WARPS_PER_BLOCK + warp;

    // ---- setup: init-row table (prescaled: 0.5 on i,f,o; 1.0 on g) ----
    if (tid < 96) {
        int s = tid >> 5;        // 0,1 = spin rows, 2 = bh-only (t=0)
        int j = tid & 31;
        float ai = bh[j], af = bh[32 + j], ag = bh[64 + j], ao = bh[96 + j];
        if (s < 2) {
            ai += Wi[s * 128 + j];
            af += Wi[s * 128 + 32 + j];
            ag += Wi[s * 128 + 64 + j];
            ao += Wi[s * 128 + 96 + j];
        }
        ulonglong2 v;
        v.x = pack2(0.5f * ai, 0.5f * af);
        v.y = pack2(ag, 0.5f * ao);
        s_init[s * 32 + j] = v;
    }
    {
        const int base = blockIdx.x * WARPS_PER_BLOCK * LL;
        for (int idx = tid; idx < WARPS_PER_BLOCK * LL; idx += THREADS_PER_BLOCK)
            s_x[idx] = (unsigned char)x[base + idx];
    }
    __syncthreads();

    const unsigned char* xb = s_x + warp * LL;
    const int j = lane;

    // ---- register-resident recurrent weights (prescaled) ----
    unsigned long long wif[32], wgo[32];
#pragma unroll
    for (int k = 0; k < 32; k++) {
        const float* r = Wh + k * 128;
        wif[k] = pack2(0.5f * r[j], 0.5f * r[32 + j]);
        wgo[k] = pack2(r[64 + j], 0.5f * r[96 + j]);
    }
    const float wo0 = Wo[2 * j];
    const float wo1 = Wo[2 * j + 1];
    const float bo0 = bo[0];
    const float bo1 = bo[1];

    float h = 0.f, c = 0.f, logp = 0.f;
    float wmask = 0.f;                       // masks the priming pend
    unsigned long long pp_pend = 0ull;       // staged (h*wo0, h*wo1)
    int cur_pend = 0;                        // spin of the staged step

    // t=0 gate init: bh-only row (row 2)
    ulonglong2 v0 = s_init[2 * 32 + lane];
    unsigned long long selif = v0.x;
    unsigned long long selgo = v0.y;

    const ulonglong2* hb0 = reinterpret_cast<const ulonglong2*>(s_h[warp][0]);
    const ulonglong2* hb1 = reinterpret_cast<const ulonglong2*>(s_h[warp][1]);

#pragma unroll 1
    for (int t = 0; t < LL; t += 2) {
#pragma unroll
        for (int half = 0; half < 2; half++) {
            // publish my (h, h) pair to this step's buffer
            s_h[warp][half][lane] = pack2(h, h);
            __syncwarp();
            const ulonglong2* hb = half ? hb1 : hb0;

            // ---- deferred output head of the PREVIOUS step ----
            // (independent of everything below; its SHFL/MUFU latency
            //  overlaps the FMA loop on other pipes)
            logp = head_update(pp_pend, cur_pend, bo0, bo1, wmask, logp);

            // ---- gate fma loop: 4 independent accumulator chains ----
            unsigned long long aif_a = selif, aif_b = 0ull;
            unsigned long long ago_a = selgo, ago_b = 0ull;
#pragma unroll
            for (int k = 0; k < 32; k += 2) {
                ulonglong2 hh = hb[k >> 1];   // broadcast LDS.128
                aif_a = fma2(hh.x, wif[k], aif_a);
                ago_a = fma2(hh.x, wgo[k], ago_a);
                aif_b = fma2(hh.y, wif[k + 1], aif_b);
                ago_b = fma2(hh.y, wgo[k + 1], ago_b);
            }
            unsigned long long aif = add2(aif_a, aif_b);
            unsigned long long ago = add2(ago_a, ago_b);

            float gi, gf, gg, go;
            unpack2(aif, gi, gf);
            unpack2(ago, gg, go);
            float si = fmaf(0.5f, tanh_fast(gi), 0.5f);   // prescaled sigmoid
            float sf = fmaf(0.5f, tanh_fast(gf), 0.5f);
            float so = fmaf(0.5f, tanh_fast(go), 0.5f);
            float tg = tanh_fast(gg);
            c = fmaf(sf, c, si * tg);
            h = so * tanh_fast(c);

            // ---- stage this step's output head for the next iteration ----
            pp_pend = pack2(h * wo0, h * wo1);
            int cur = (int)xb[t + half];
            cur_pend = cur;
            wmask = 1.f;

            // next step's gate-init row (selected by this step's spin)
            ulonglong2 vn = s_init[cur * 32 + lane];
            selif = vn.x;
            selgo = vn.y;
        }
    }

    // flush the last step's pend
    logp = head_update(pp_pend, cur_pend, bo0, bo1, wmask, logp);

    if (lane == 0) {
        out[b_glob] = 0.5f * logp;
    }
}

extern "C" void kernel_launch(void* const* d_in, const int* in_sizes, int n_in,
                              void* d_out, int out_size) {
    const int* x = (const int*)d_in[0];
    const float* Wi = (const float*)d_in[1];
    const float* Wh = (const float*)d_in[2];
    const float* bh = (const float*)d_in[3];
    const float* Wo = (const float*)d_in[4];
    const float* bo = (const float*)d_in[5];
    float* out = (float*)d_out;

    const int batch = in_sizes[0] / LL;                 // 4096
    const int blocks = batch / WARPS_PER_BLOCK;         // 1024

    lstm_kernel<<<blocks, THREADS_PER_BLOCK>>>(x, Wi, Wh, bh, Wo, bo, out);
}